// round 10
// baseline (speedup 1.0000x reference)
#include <cuda_runtime.h>
#include <cuda_bf16.h>
#include <stdint.h>

// ---------------- problem constants ----------------
#define NQ       600
#define NQPAD    640
#define NCLS     81
#define LPIX     65536
#define MT       50
#define MTP      64
#define TILEQ    64
#define GRID296  296      // 148 SMs x occ 2 = one wave
#define KCHUNK   64
#define NC2      1024     // LPIX / KCHUNK
#define KSLOT    32       // partial-slot stride (max slots per y-tile = 30)
#define STR72    72       // smem row stride in bf16 elems (144B)
#define TBUF     9216     // bytes per tile buffer (64 rows x 72 x 2B)
#define SMEM_DYN (7 * TBUF)   // sA1[2] + sA2[2] + sB[3] = 64512 bytes

// ---------------- scratch (__device__ globals; no runtime allocation) ----------------
__device__ float g_part_pn[NQPAD][KSLOT][MTP];
__device__ float g_part_p [NQPAD][KSLOT][MTP];
__device__ float g_part_ns[NQPAD][KSLOT];
__device__ __nv_bfloat16 g_bexp[NC2][MTP][KCHUNK];   // expanded B (col 63 = ones), 8 MB
__device__ int g_tsump[MTP][32];                     // per-target pixel count partials
__device__ int g_done[10];                           // y-tile tickets (self-resetting)

// ---------------- kernel 1: expand masks to bf16 B tiles + count partials ---------
// grid (32, 64): by = target row n, each block covers 2048 pixels.
__global__ void prep_kernel(const int* __restrict__ tmasks)
{
    const int n    = blockIdx.y;
    const int tid  = threadIdx.x;
    const int lane = tid & 31;
    __shared__ int scnt[8];

    const float fill = (n == 63) ? 1.0f : 0.0f;   // column 63 = ones (row-sum trick)
    int cnt = 0;
#pragma unroll
    for (int it = 0; it < 4; it++) {
        const int pair = blockIdx.x * 1024 + it * 256 + tid;
        const int j    = pair * 2;
        float f0 = fill, f1 = fill;
        if (n < MT) {
            int2 vv = *reinterpret_cast<const int2*>(tmasks + (size_t)n * LPIX + j);
            f0 = vv.x ? 1.0f : 0.0f;
            f1 = vv.y ? 1.0f : 0.0f;
            cnt += (vv.x != 0) + (vv.y != 0);
        }
        *reinterpret_cast<__nv_bfloat162*>(&g_bexp[j >> 6][n][j & 63]) =
            __floats2bfloat162_rn(f0, f1);
    }
#pragma unroll
    for (int o = 16; o; o >>= 1) cnt += __shfl_xor_sync(0xffffffffu, cnt, o);
    if (lane == 0) scnt[tid >> 5] = cnt;
    __syncthreads();
    if (tid == 0) {
        int t = 0;
#pragma unroll
        for (int k = 0; k < 8; k++) t += scnt[k];
        g_tsump[n][blockIdx.x] = t;
    }
}

// ---------------- asm helpers ----------------
__device__ __forceinline__ float fex2(float x) { float r; asm("ex2.approx.f32 %0,%1;" : "=f"(r) : "f"(x)); return r; }
__device__ __forceinline__ float flg2(float x) { float r; asm("lg2.approx.f32 %0,%1;" : "=f"(r) : "f"(x)); return r; }
__device__ __forceinline__ float frcp(float x) { float r; asm("rcp.approx.f32 %0,%1;" : "=f"(r) : "f"(x)); return r; }

__device__ __forceinline__ void ldmatrix_x4(uint32_t* r, uint32_t addr)
{
    asm volatile("ldmatrix.sync.aligned.m8n8.x4.shared.b16 {%0,%1,%2,%3}, [%4];"
                 : "=r"(r[0]), "=r"(r[1]), "=r"(r[2]), "=r"(r[3]) : "r"(addr));
}

__device__ __forceinline__ void mma_bf16(float* d, const uint32_t* a, uint32_t b0, uint32_t b1)
{
    asm volatile(
        "mma.sync.aligned.m16n8k16.row.col.f32.bf16.bf16.f32 "
        "{%0,%1,%2,%3}, {%4,%5,%6,%7}, {%8,%9}, {%0,%1,%2,%3};"
        : "+f"(d[0]), "+f"(d[1]), "+f"(d[2]), "+f"(d[3])
        : "r"(a[0]), "r"(a[1]), "r"(a[2]), "r"(a[3]), "r"(b0), "r"(b1));
}

__device__ __forceinline__ void cpa16(uint32_t dst, const void* src)
{
    asm volatile("cp.async.cg.shared.global [%0], [%1], 16;" :: "r"(dst), "l"(src));
}
__device__ __forceinline__ void cp_commit() { asm volatile("cp.async.commit_group;" ::: "memory"); }
__device__ __forceinline__ void cp_wait1()  { asm volatile("cp.async.wait_group 1;" ::: "memory"); }
__device__ __forceinline__ void cp_wait0()  { asm volatile("cp.async.wait_group 0;" ::: "memory"); }

// focal/sigmoid transform
__device__ __forceinline__ void txf(float x, float& pn, float& p, float& nT)
{
    float e = fex2(x * -1.44269504f);      // e^{-x}
    float u = 1.0f + e;
    p = frcp(u);                           // sigmoid(x)
    float s = flg2(u) * 0.69314718056f;    // softplus(-x)
    float o = 1.0f - p;
    float P = s * o * o;
    float T = (x + s) * (p * p);
    nT = T * 0.75f;
    pn = fmaf(P, 0.25f, -nT);
}

// ---------------- kernel 2: transform + MMA + fused epilogue ----------------------
// Dynamic smem layout (64512 B): [0) sA1[2][64][72], [18432) sA2[2][64][72],
// [36864) sB[3][64][72] -- all bf16.
__global__ void __launch_bounds__(256, 2) main_mma_kernel(
    const float* __restrict__ pm, const float* __restrict__ logits,
    const float* __restrict__ pboxes, const float* __restrict__ tboxes,
    const int* __restrict__ tlabels, const int* __restrict__ osize,
    float* __restrict__ out)
{
    extern __shared__ __align__(16) char dsm[];
    __nv_bfloat16* sA1 = reinterpret_cast<__nv_bfloat16*>(dsm);              // 2 bufs
    __nv_bfloat16* sA2 = reinterpret_cast<__nv_bfloat16*>(dsm + 2 * TBUF);   // 2 bufs
    __nv_bfloat16* sB  = reinterpret_cast<__nv_bfloat16*>(dsm + 4 * TBUF);   // 3 bufs

    __shared__ float eq[4][TILEQ];     // epilogue: max, den, ns, ps per query
    __shared__ int   etsum[MTP];
    __shared__ int   elast;

    const int tid  = threadIdx.x;
    const int lane = tid & 31;
    const int w    = tid >> 5;
    const int bid  = blockIdx.x;

    const int yy    = (bid * 10 + 9) / 296;
    const int ybase = (yy * 296) / 10;
    const int slot  = bid - ybase;
    const int ny    = ((yy + 1) * 296) / 10 - ybase;
    const int c0    = (slot * NC2) / ny;
    const int c1    = ((slot + 1) * NC2) / ny;
    const int rowbase = yy * TILEQ;

    const int r_sub = lane >> 4;
    const int kl    = lane & 15;
    const int m0    = (w & 3) * 16;
    const int nhalf = (w >> 2) * 32;
    const int gq    = lane >> 2;
    const int c4    = lane & 3;

    float d1[4][4];
    float d2[4][4];
#pragma unroll
    for (int j = 0; j < 4; j++) {
#pragma unroll
        for (int i = 0; i < 4; i++) { d1[j][i] = 0.0f; d2[j][i] = 0.0f; }
    }
    float accn[4] = {0.0f, 0.0f, 0.0f, 0.0f};

    // per-thread source rows: rowbase + w*8 + 2*i + r_sub (clamped; garbage unread)
    const float* rowp[4];
#pragma unroll
    for (int i = 0; i < 4; i++) {
        int row = rowbase + w * 8 + 2 * i + r_sub;
        if (row > 599) row = 599;
        rowp[i] = pm + (size_t)row * LPIX + kl * 4;
    }

    const uint32_t sa1b = (uint32_t)__cvta_generic_to_shared(sA1);
    const uint32_t sa2b = (uint32_t)__cvta_generic_to_shared(sA2);
    const uint32_t sbb  = (uint32_t)__cvta_generic_to_shared(sB);

    const uint32_t aoff  = (uint32_t)(((m0 + (lane & 15)) * STR72 + (lane >> 4) * 8) * 2);
    const int nrow0      = nhalf + ((lane >> 4) & 1) * 8 + (lane & 7);
    const uint32_t boff0 = (uint32_t)((nrow0 * STR72 + ((lane >> 3) & 1) * 8) * 2);
    const uint32_t boff1 = boff0 + (uint32_t)(16 * STR72 * 2);

    const int stg_n = tid >> 2;
    const int stg_s = tid & 3;

    auto stageB = [&](int c, int b) {
        const uint32_t base = sbb + (uint32_t)b * TBUF + (uint32_t)(stg_n * STR72 * 2);
        cpa16(base + stg_s * 16,       &g_bexp[c][stg_n][stg_s * 8]);
        cpa16(base + (stg_s + 4) * 16, &g_bexp[c][stg_n][(stg_s + 4) * 8]);
        cp_commit();
    };
    auto loadpx = [&](float4* x, int c) {
#pragma unroll
        for (int i = 0; i < 4; i++)
            x[i] = *reinterpret_cast<const float4*>(rowp[i] + c * KCHUNK);
    };
    auto xform = [&](const float4* x, int b) {
#pragma unroll
        for (int i = 0; i < 4; i++) {
            float pn0, p0, n0, pn1, p1, n1, pn2, p2, n2, pn3, p3, n3;
            txf(x[i].x, pn0, p0, n0);
            txf(x[i].y, pn1, p1, n1);
            txf(x[i].z, pn2, p2, n2);
            txf(x[i].w, pn3, p3, n3);
            accn[i] += (n0 + n1) + (n2 + n3);
            const int rr = w * 8 + 2 * i + r_sub;
            __nv_bfloat16* a1 = sA1 + b * (TBUF / 2) + rr * STR72 + kl * 4;
            __nv_bfloat16* a2 = sA2 + b * (TBUF / 2) + rr * STR72 + kl * 4;
            *reinterpret_cast<__nv_bfloat162*>(a1)     = __floats2bfloat162_rn(pn0, pn1);
            *reinterpret_cast<__nv_bfloat162*>(a1 + 2) = __floats2bfloat162_rn(pn2, pn3);
            *reinterpret_cast<__nv_bfloat162*>(a2)     = __floats2bfloat162_rn(p0, p1);
            *reinterpret_cast<__nv_bfloat162*>(a2 + 2) = __floats2bfloat162_rn(p2, p3);
        }
    };
    auto mmaStep = [&](int bA, int bB) {
        const uint32_t aB  = (uint32_t)bA * TBUF;
        const uint32_t bBo = (uint32_t)bB * TBUF;
#pragma unroll
        for (int h = 0; h < 4; h++) {
            uint32_t a1r[4], a2r[4], bL[4], bH[4];
            ldmatrix_x4(a1r, sa1b + aB + aoff + h * 32);
            ldmatrix_x4(a2r, sa2b + aB + aoff + h * 32);
            ldmatrix_x4(bL,  sbb  + bBo + boff0 + h * 32);
            ldmatrix_x4(bH,  sbb  + bBo + boff1 + h * 32);
            mma_bf16(d1[0], a1r, bL[0], bL[1]);
            mma_bf16(d2[0], a2r, bL[0], bL[1]);
            mma_bf16(d1[1], a1r, bL[2], bL[3]);
            mma_bf16(d2[1], a2r, bL[2], bL[3]);
            mma_bf16(d1[2], a1r, bH[0], bH[1]);
            mma_bf16(d2[2], a2r, bH[0], bH[1]);
            mma_bf16(d1[3], a1r, bH[2], bH[3]);
            mma_bf16(d2[3], a2r, bH[2], bH[3]);
        }
    };

    // ---- prologue: B pipeline depth 2; A buffer 0 ----
    // note: chunks per CTA ~= 1024/30 >= 34, so c0+1 < c1 always holds.
    float4 xv[4];
    float4 xn[4];
    stageB(c0, 0);
    stageB(c0 + 1, 1);
    loadpx(xv, c0);
    loadpx(xn, c0 + 1);
    xform(xv, 0);
    cp_wait1();
    __syncthreads();

    for (int c = c0; c < c1; c++) {
        const int cur = c - c0;
        const int bA  = cur & 1;
        const bool hn = (c + 1 < c1);
        if (c + 2 < c1) stageB(c + 2, (cur + 2) % 3);
        float4 xf[4];
        loadpx(xf, (c + 2 < c1) ? c + 2 : c1 - 1);
        if (hn) xform(xn, bA ^ 1);
        mmaStep(bA, cur % 3);
        if (c + 2 < c1) cp_wait1(); else cp_wait0();
        __syncthreads();
#pragma unroll
        for (int i = 0; i < 4; i++) xn[i] = xf[i];
    }

    // ---- write partials ----
#pragma unroll
    for (int j = 0; j < 4; j++) {
        const int row = rowbase + m0 + gq;
        const int col = nhalf + j * 8 + c4 * 2;
        *reinterpret_cast<float2*>(&g_part_pn[row][slot][col])     = make_float2(d1[j][0], d1[j][1]);
        *reinterpret_cast<float2*>(&g_part_pn[row + 8][slot][col]) = make_float2(d1[j][2], d1[j][3]);
        *reinterpret_cast<float2*>(&g_part_p [row][slot][col])     = make_float2(d2[j][0], d2[j][1]);
        *reinterpret_cast<float2*>(&g_part_p [row + 8][slot][col]) = make_float2(d2[j][2], d2[j][3]);
    }
#pragma unroll
    for (int i = 0; i < 4; i++) {
        float rn = accn[i];
#pragma unroll
        for (int o = 8; o; o >>= 1) rn += __shfl_xor_sync(0xffffffffu, rn, o);
        if ((lane & 15) == 0)
            g_part_ns[rowbase + w * 8 + 2 * i + r_sub][slot] = rn;
    }

    // ---- fused epilogue: last CTA of this y-tile finishes its 64 queries ----
    __threadfence();
    __syncthreads();
    if (tid == 0) {
        int old = atomicAdd(&g_done[yy], 1);
        elast = (old == ny - 1) ? 1 : 0;
    }
    __syncthreads();
    if (!elast) return;
    __threadfence();

    if (tid < MTP) {
        int t = 0;
#pragma unroll
        for (int s = 0; s < 32; s++) t += g_tsump[tid][s];
        etsum[tid] = t;
    }

    // per-query scalars: warp w handles queries w*8 .. w*8+7
#pragma unroll 1
    for (int r = 0; r < 8; r++) {
        const int qloc = w * 8 + r;
        const int q    = rowbase + qloc;
        const int qc   = (q < NQ) ? q : (NQ - 1);
        float mx = -1e30f;
        for (int cc = lane; cc < NCLS; cc += 32) mx = fmaxf(mx, logits[qc * NCLS + cc]);
#pragma unroll
        for (int o = 16; o; o >>= 1) mx = fmaxf(mx, __shfl_xor_sync(0xffffffffu, mx, o));
        float den = 0.0f;
        for (int cc = lane; cc < NCLS; cc += 32) den += __expf(logits[qc * NCLS + cc] - mx);
        float ns = 0.0f;
        float ps = 0.0f;
        if (lane < ny) {
            ns = g_part_ns[qc][lane];
            ps = g_part_p [qc][lane][63];
        }
#pragma unroll
        for (int o = 16; o; o >>= 1) {
            den += __shfl_xor_sync(0xffffffffu, den, o);
            ns  += __shfl_xor_sync(0xffffffffu, ns, o);
            ps  += __shfl_xor_sync(0xffffffffu, ps, o);
        }
        if (lane == 0) {
            eq[0][qloc] = mx;
            eq[1][qloc] = den;
            eq[2][qloc] = ns;
            eq[3][qloc] = ps;
        }
    }
    __syncthreads();

    const float Wn = (float)osize[1];
    const float Hn = (float)osize[0];
    for (int idx = tid; idx < TILEQ * MT; idx += 256) {
        const int qloc = idx / MT;
        const int m    = idx - qloc * MT;
        const int q    = rowbase + qloc;
        if (q >= NQ) continue;
        float spn = 0.0f;
        float sp  = 0.0f;
        for (int s = 0; s < ny; s++) {
            spn += g_part_pn[q][s][m];
            sp  += g_part_p [q][s][m];
        }
        const float cmask = (spn + eq[2][qloc]) * (1.0f / (float)LPIX);
        const float cdice = 1.0f - (2.0f * sp + 1.0f) / (eq[3][qloc] + (float)etsum[m] + 1.0f);
        const int   lab   = tlabels[m];
        const float cclass = -__expf(logits[q * NCLS + lab] - eq[0][qloc]) / eq[1][qloc];
        const float tx = tboxes[m * 4 + 0];
        const float ty = tboxes[m * 4 + 1];
        const float tw = tboxes[m * 4 + 2];
        const float th = tboxes[m * 4 + 3];
        const float ncx = (tx + 0.5f * tw) / Wn;
        const float ncy = (ty + 0.5f * th) / Hn;
        const float nwv = tw / Wn;
        const float nhv = th / Hn;
        const float* pb = pboxes + q * 4;
        const float cb = fabsf(pb[0] - ncx) + fabsf(pb[1] - ncy)
                       + fabsf(pb[2] - nwv) + fabsf(pb[3] - nhv);
        out[q * MT + m] = 2.0f * cclass + 5.0f * cmask + 5.0f * cdice + 5.0f * cb;
    }

    // reset ticket for the next launch/replay (all CTAs of this y-tile already arrived)
    __syncthreads();
    if (tid == 0) g_done[yy] = 0;
}

// ---------------- launch ----------------------------------------------------------
extern "C" void kernel_launch(void* const* d_in, const int* in_sizes, int n_in,
                              void* d_out, int out_size)
{
    const float* logits  = (const float*)d_in[0];
    const float* pmasks  = (const float*)d_in[1];
    const float* pboxes  = (const float*)d_in[2];
    const float* tboxes  = (const float*)d_in[3];
    const int*   tlabels = (const int*)d_in[4];
    const int*   tmasks  = (const int*)d_in[5];
    const int*   osize   = (const int*)d_in[6];
    float* out = (float*)d_out;

    // opt in to >48KB dynamic smem (attribute set: no allocation, no stream op)
    cudaFuncSetAttribute(main_mma_kernel,
                         cudaFuncAttributeMaxDynamicSharedMemorySize, SMEM_DYN);

    prep_kernel<<<dim3(32, 64), 256>>>(tmasks);
    main_mma_kernel<<<GRID296, 256, SMEM_DYN>>>(pmasks, logits, pboxes, tboxes,
                                                tlabels, osize, out);
}